// round 4
// baseline (speedup 1.0000x reference)
#include <cuda_runtime.h>
#include <math.h>

// Problem constants
#define VOCAB 32000
#define E_DIM 256
#define H_DIM 256
#define BATCH 64
#define T_LEN 2048
#define NCH 16                 // time chunks for parallel scan
#define TC (T_LEN / NCH)       // 128 timesteps per chunk

// ---------------- device scratch (allocation-free contract) ----------------
// Gate tables, post-activation, per vocab row: Gz[v][h] = tanh(.), Gf[v][h] = sigmoid(.)
__device__ float g_Gz[(size_t)VOCAB * H_DIM];   // 32.8 MB
__device__ float g_Gf[(size_t)VOCAB * H_DIM];   // 32.8 MB
// Per-(b,chunk) scan coefficients: c_out = A*c_in + B
__device__ float g_cA[BATCH * NCH * H_DIM];     // 1.05 MB
__device__ float g_cB[BATCH * NCH * H_DIM];     // 1.05 MB

// ---------------------------------------------------------------------------
// Kernel 1: G[v, 0:512] = emb[v,:] @ W_qrnn[:, 0:512] + b, then activation.
// Classic 128x128 tiled SGEMM, BK=16, 8x8 microtile, 256 threads.
// M=32000, N=512, K=256 all divide tile sizes exactly.
// ---------------------------------------------------------------------------
#define BM 128
#define BN 128
#define BK 16

__global__ __launch_bounds__(256, 2) void gemm_gates(
    const float* __restrict__ emb,   // [VOCAB, 256]
    const float* __restrict__ W,     // [256, 768] row-major
    const float* __restrict__ bias)  // [768]
{
    __shared__ float As[BK][BM];
    __shared__ float Bs[BK][BN];

    const int tid = threadIdx.x;
    const int n0  = blockIdx.x * BN;   // 0..511 (grid.x = 4)
    const int m0  = blockIdx.y * BM;   // vocab row base (grid.y = 250)

    const int tx = tid & 15;           // 0..15  (n microtile group)
    const int ty = tid >> 4;           // 0..15  (m microtile group)

    // A-tile load mapping: 2 float4 per thread
    const int arow = tid >> 2;         // 0..63
    const int acol = (tid & 3) * 4;    // 0,4,8,12
    // B-tile load mapping: 2 float4 per thread
    const int brow = tid >> 5;         // 0..7
    const int bcol = (tid & 31) * 4;   // 0..124

    float acc[8][8];
    #pragma unroll
    for (int i = 0; i < 8; i++)
        #pragma unroll
        for (int j = 0; j < 8; j++) acc[i][j] = 0.f;

    const float* Aptr = emb + (size_t)m0 * E_DIM;

    for (int k0 = 0; k0 < E_DIM; k0 += BK) {
        // Load A tile (transposed into As[k][m])
        #pragma unroll
        for (int i = 0; i < 2; i++) {
            int m = arow + i * 64;
            float4 v = *(const float4*)(Aptr + (size_t)m * E_DIM + k0 + acol);
            As[acol + 0][m] = v.x;
            As[acol + 1][m] = v.y;
            As[acol + 2][m] = v.z;
            As[acol + 3][m] = v.w;
        }
        // Load B tile
        #pragma unroll
        for (int i = 0; i < 2; i++) {
            int k = brow + i * 8;
            float4 v = *(const float4*)(W + (size_t)(k0 + k) * 768 + n0 + bcol);
            *(float4*)&Bs[k][bcol] = v;
        }
        __syncthreads();

        #pragma unroll
        for (int k = 0; k < BK; k++) {
            float a[8], bb[8];
            float4 a0 = *(const float4*)&As[k][ty * 4];
            float4 a1 = *(const float4*)&As[k][64 + ty * 4];
            float4 b0 = *(const float4*)&Bs[k][tx * 4];
            float4 b1 = *(const float4*)&Bs[k][64 + tx * 4];
            a[0]=a0.x; a[1]=a0.y; a[2]=a0.z; a[3]=a0.w;
            a[4]=a1.x; a[5]=a1.y; a[6]=a1.z; a[7]=a1.w;
            bb[0]=b0.x; bb[1]=b0.y; bb[2]=b0.z; bb[3]=b0.w;
            bb[4]=b1.x; bb[5]=b1.y; bb[6]=b1.z; bb[7]=b1.w;
            #pragma unroll
            for (int i = 0; i < 8; i++)
                #pragma unroll
                for (int j = 0; j < 8; j++)
                    acc[i][j] = fmaf(a[i], bb[j], acc[i][j]);
        }
        __syncthreads();
    }

    // Epilogue: bias + activation, scatter into Gz / Gf tables
    #pragma unroll
    for (int i = 0; i < 8; i++) {
        int m = m0 + ((i < 4) ? (ty * 4 + i) : (64 + ty * 4 + (i - 4)));
        #pragma unroll
        for (int j = 0; j < 8; j++) {
            int n = n0 + ((j < 4) ? (tx * 4 + j) : (64 + tx * 4 + (j - 4)));
            float val = acc[i][j] + __ldg(&bias[n]);
            if (n < H_DIM) {
                g_Gz[(size_t)m * H_DIM + n] = tanhf(val);
            } else {
                g_Gf[(size_t)m * H_DIM + (n - H_DIM)] = 1.f / (1.f + expf(-val));
            }
        }
    }
}

// ---------------------------------------------------------------------------
// Kernel 2: parallel chunked scan. Each CTA = (chunk, b), 256 threads (1 per h).
// Computes A = prod f_t, B = local recurrence from 0 over its 128 timesteps.
// Gate values gathered from the vocab tables (coalesced across h, L2-resident).
// ---------------------------------------------------------------------------
__global__ __launch_bounds__(256) void scan_chunks(const int* __restrict__ X)
{
    const int chunk = blockIdx.x;
    const int b     = blockIdx.y;
    const int h     = threadIdx.x;

    __shared__ int toks[TC];
    if (h < TC) toks[h] = __ldg(&X[b * T_LEN + chunk * TC + h]);
    __syncthreads();

    float A = 1.f, Bc = 0.f;
    #pragma unroll 16
    for (int t = 0; t < TC; t++) {
        size_t base = (size_t)toks[t] * H_DIM + h;
        float f = __ldg(&g_Gf[base]);
        float z = __ldg(&g_Gz[base]);
        A *= f;
        // c = f*c + (1-f)*z  ==  f*(c - z) + z
        Bc = fmaf(f, Bc - z, z);
    }

    int idx = (b * NCH + chunk) * H_DIM + h;
    g_cA[idx] = A;
    g_cB[idx] = Bc;
}

// ---------------------------------------------------------------------------
// Kernel 3: sequential chunk combine (16 steps), o-gate for the last token,
// and the final H->1 projection with block reduction. One CTA per batch row.
// ---------------------------------------------------------------------------
__global__ __launch_bounds__(256) void finalize(
    const int*   __restrict__ X,
    const float* __restrict__ emb,
    const float* __restrict__ W,      // [256, 768]
    const float* __restrict__ bias,   // [768]
    const float* __restrict__ c0,     // [B, H]
    const float* __restrict__ Wout,   // [H]
    const float* __restrict__ bout,   // [1]
    float*       __restrict__ out)    // [B]
{
    const int b = blockIdx.x;
    const int h = threadIdx.x;

    __shared__ float xrow[E_DIM];
    __shared__ float red[H_DIM];

    const int tok_last = X[b * T_LEN + (T_LEN - 1)];
    xrow[h] = emb[(size_t)tok_last * E_DIM + h];
    __syncthreads();

    // Combine chunks in time order
    float c = c0[b * H_DIM + h];
    #pragma unroll
    for (int j = 0; j < NCH; j++) {
        int idx = (b * NCH + j) * H_DIM + h;
        c = fmaf(g_cA[idx], c, g_cB[idx]);
    }

    // o_{T-1}[h] = sigmoid(emb[tok_last] . W[:, 512+h] + bias[512+h])
    float a0 = bias[512 + h], a1 = 0.f, a2 = 0.f, a3 = 0.f;
    #pragma unroll 8
    for (int e = 0; e < E_DIM; e += 4) {
        a0 = fmaf(xrow[e + 0], W[(size_t)(e + 0) * 768 + 512 + h], a0);
        a1 = fmaf(xrow[e + 1], W[(size_t)(e + 1) * 768 + 512 + h], a1);
        a2 = fmaf(xrow[e + 2], W[(size_t)(e + 2) * 768 + 512 + h], a2);
        a3 = fmaf(xrow[e + 3], W[(size_t)(e + 3) * 768 + 512 + h], a3);
    }
    float go = (a0 + a1) + (a2 + a3);
    float o  = 1.f / (1.f + expf(-go));

    red[h] = o * c * Wout[h];
    __syncthreads();

    #pragma unroll
    for (int s = 128; s > 0; s >>= 1) {
        if (h < s) red[h] += red[h + s];
        __syncthreads();
    }
    if (h == 0) out[b] = red[0] + bout[0];
}

// ---------------------------------------------------------------------------
extern "C" void kernel_launch(void* const* d_in, const int* in_sizes, int n_in,
                              void* d_out, int out_size)
{
    const int*   X    = (const int*)  d_in[0];   // [B, T] int32
    const float* emb  = (const float*)d_in[1];   // [VOCAB, E]
    const float* Wq   = (const float*)d_in[2];   // [E, 3H]
    const float* bq   = (const float*)d_in[3];   // [3H]
    const float* c0   = (const float*)d_in[4];   // [B, H]
    const float* Wout = (const float*)d_in[5];   // [H, 1]
    const float* bout = (const float*)d_in[6];   // [1]
    float*       out  = (float*)d_out;           // [B, 1]

    (void)in_sizes; (void)n_in; (void)out_size;

    // 1) Vocab-wide gate table GEMM (z, f only; o handled in finalize)
    dim3 ggrid(512 / BN, VOCAB / BM);            // (4, 250)
    gemm_gates<<<ggrid, 256>>>(emb, Wq, bq);

    // 2) Parallel chunked scan over time
    dim3 sgrid(NCH, BATCH);                      // (16, 64)
    scan_chunks<<<sgrid, 256>>>(X);

    // 3) Combine + o-gate + output projection
    finalize<<<BATCH, 256>>>(X, emb, Wq, bq, c0, Wout, bout, out);
}

// round 6
// speedup vs baseline: 1.5529x; 1.5529x over previous
#include <cuda_runtime.h>
#include <cuda_bf16.h>
#include <math.h>
#include <stdint.h>

// Problem constants
#define VOCAB 32000
#define E_DIM 256
#define H_DIM 256
#define BATCH 64
#define T_LEN 2048
#define NCH 16                 // time chunks for parallel scan
#define TC (T_LEN / NCH)       // 128 timesteps per chunk

// ---------------- device scratch (allocation-free contract) ----------------
__device__ float g_Gz[(size_t)VOCAB * H_DIM];        // tanh(z) table, 32.8 MB
__device__ float g_Gf[(size_t)VOCAB * H_DIM];        // sigmoid(f) table, 32.8 MB
__device__ float g_cA[BATCH * NCH * H_DIM];          // per-chunk scan coeff A
__device__ float g_cB[BATCH * NCH * H_DIM];          // per-chunk scan coeff B
__device__ __nv_bfloat16 g_Abf[(size_t)VOCAB * 512]; // [Ah(256) | Al(256)] per row
__device__ __nv_bfloat16 g_Bbf[(size_t)512 * 768];   // [n][ Bh | Bh | Bl ] (k-contig)

static __device__ __forceinline__ uint32_t smem_u32(const void* p) {
    uint32_t a;
    asm("{ .reg .u64 t; cvta.to.shared.u64 t, %1; cvt.u32.u64 %0, t; }" : "=r"(a) : "l"(p));
    return a;
}

// ===========================================================================
// Convert kernels: fp32 -> 2-term bf16 split, GEMM-friendly layouts.
// ===========================================================================
__global__ __launch_bounds__(256) void convert_A(const float* __restrict__ emb)
{
    int idx = blockIdx.x * 256 + threadIdx.x;   // one float4 each; 32000*64 total
    int v = idx >> 6;
    int k = (idx & 63) * 4;
    float4 x = *(const float4*)(emb + (size_t)v * E_DIM + k);
    __nv_bfloat162 h01 = __floats2bfloat162_rn(x.x, x.y);
    __nv_bfloat162 h23 = __floats2bfloat162_rn(x.z, x.w);
    __nv_bfloat162 l01 = __floats2bfloat162_rn(x.x - __bfloat162float(h01.x),
                                               x.y - __bfloat162float(h01.y));
    __nv_bfloat162 l23 = __floats2bfloat162_rn(x.z - __bfloat162float(h23.x),
                                               x.w - __bfloat162float(h23.y));
    __nv_bfloat16* row = g_Abf + (size_t)v * 512;
    *(__nv_bfloat162*)(row + k)           = h01;
    *(__nv_bfloat162*)(row + k + 2)       = h23;
    *(__nv_bfloat162*)(row + 256 + k)     = l01;
    *(__nv_bfloat162*)(row + 256 + k + 2) = l23;
}

__global__ __launch_bounds__(512) void convert_B(const float* __restrict__ W)
{
    int k = blockIdx.x;          // 0..255 (W row)
    int n = threadIdx.x;         // 0..511 (gate column, z then f)
    float v = W[(size_t)k * 768 + n];
    __nv_bfloat16 h = __float2bfloat16(v);
    __nv_bfloat16 l = __float2bfloat16(v - __bfloat162float(h));
    __nv_bfloat16* row = g_Bbf + (size_t)n * 768;
    row[k]       = h;   // pairs with Ah (iters 0-7)
    row[k + 256] = h;   // pairs with Al (iters 8-15)
    row[k + 512] = l;   // pairs with Ah (iters 16-23)
}

// ===========================================================================
// Kernel 1: bf16 split GEMM on classic tensor cores (mma.sync m16n8k16).
// D[128x128 per CTA] over K'=768 (24 iters of BK=32), double-buffered cp.async.
// A smem [m][k] 80B rows; B smem [n][k] 80B rows (n-major = col-major B).
// 8 warps: warp_m = wid&1 (64 rows), warp_n = wid>>1 (32 cols).
// ===========================================================================
#define SZT (128 * 80)   // one stage of one tile (padded rows: 64B data + 16B pad)

__global__ __launch_bounds__(256, 2) void gemm_gates_mma(const float* __restrict__ bias)
{
    __shared__ __align__(128) char sA[2][SZT];
    __shared__ __align__(128) char sB[2][SZT];
    __shared__ float sbias[128];

    const int tid  = threadIdx.x;
    const int lane = tid & 31;
    const int wid  = tid >> 5;
    const int n0   = blockIdx.x * 128;   // 0,128 -> z table; 256,384 -> f table
    const int m0   = blockIdx.y * 128;   // vocab row base
    const int warp_m = wid & 1;
    const int warp_n = wid >> 1;

    if (tid < 32) *(float4*)&sbias[tid * 4] = *(const float4*)&bias[n0 + tid * 4];

    const uint32_t sAu = smem_u32(sA);
    const uint32_t sBu = smem_u32(sB);

    // cp.async mapping: 512 16B-chunks per tile; row = tid>>2 (+64), chunk = tid&3
    const int ld_row = tid >> 2;
    const int ld_chk = tid & 3;

    float c[4][4][4];
    #pragma unroll
    for (int i = 0; i < 4; i++)
        #pragma unroll
        for (int j = 0; j < 4; j++)
            #pragma unroll
            for (int q = 0; q < 4; q++) c[i][j][q] = 0.f;

    // ldmatrix lane-dependent base byte-offsets (buf/kstep added later)
    const uint32_t a_lm = (uint32_t)((warp_m * 64 + (lane & 15)) * 80 + (lane >> 4) * 16);
    const uint32_t b_lm = (uint32_t)((warp_n * 32 + (lane >> 4) * 8 + (lane & 7)) * 80
                                     + ((lane >> 3) & 1) * 16);

#define ISSUE(it, buf) do {                                                        \
    int kA_ = (((it) < 16) ? (it) : (it) - 16) * 32;                               \
    int kB_ = (it) * 32;                                                           \
    _Pragma("unroll")                                                              \
    for (int r_ = 0; r_ < 2; r_++) {                                               \
        int row_ = ld_row + r_ * 64;                                               \
        uint32_t da_ = sAu + (buf) * SZT + row_ * 80 + ld_chk * 16;                \
        const __nv_bfloat16* ga_ = g_Abf + (size_t)(m0 + row_) * 512 + kA_ + ld_chk * 8; \
        asm volatile("cp.async.cg.shared.global [%0], [%1], 16;" :: "r"(da_), "l"(ga_)); \
        uint32_t db_ = sBu + (buf) * SZT + row_ * 80 + ld_chk * 16;                \
        const __nv_bfloat16* gb_ = g_Bbf + (size_t)(n0 + row_) * 768 + kB_ + ld_chk * 8; \
        asm volatile("cp.async.cg.shared.global [%0], [%1], 16;" :: "r"(db_), "l"(gb_)); \
    }                                                                              \
    asm volatile("cp.async.commit_group;");                                        \
} while (0)

    ISSUE(0, 0);

    for (int it = 0; it < 24; ++it) {
        const int buf = it & 1;
        if (it + 1 < 24) {
            ISSUE(it + 1, buf ^ 1);
            asm volatile("cp.async.wait_group 1;");
        } else {
            asm volatile("cp.async.wait_group 0;");
        }
        __syncthreads();

        #pragma unroll
        for (int ks = 0; ks < 2; ks++) {
            uint32_t a[4][4], b[4][2];
            #pragma unroll
            for (int mt = 0; mt < 4; mt++) {
                uint32_t addr = sAu + buf * SZT + a_lm + mt * (16 * 80) + ks * 32;
                asm volatile("ldmatrix.sync.aligned.m8n8.x4.shared.b16 {%0,%1,%2,%3}, [%4];"
                             : "=r"(a[mt][0]), "=r"(a[mt][1]), "=r"(a[mt][2]), "=r"(a[mt][3])
                             : "r"(addr));
            }
            #pragma unroll
            for (int np = 0; np < 2; np++) {
                uint32_t addr = sBu + buf * SZT + b_lm + np * (16 * 80) + ks * 32;
                asm volatile("ldmatrix.sync.aligned.m8n8.x4.shared.b16 {%0,%1,%2,%3}, [%4];"
                             : "=r"(b[np * 2][0]), "=r"(b[np * 2][1]),
                               "=r"(b[np * 2 + 1][0]), "=r"(b[np * 2 + 1][1])
                             : "r"(addr));
            }
            #pragma unroll
            for (int mt = 0; mt < 4; mt++)
                #pragma unroll
                for (int nt = 0; nt < 4; nt++)
                    asm volatile(
                        "mma.sync.aligned.m16n8k16.row.col.f32.bf16.bf16.f32 "
                        "{%0,%1,%2,%3}, {%4,%5,%6,%7}, {%8,%9}, {%0,%1,%2,%3};"
                        : "+f"(c[mt][nt][0]), "+f"(c[mt][nt][1]),
                          "+f"(c[mt][nt][2]), "+f"(c[mt][nt][3])
                        : "r"(a[mt][0]), "r"(a[mt][1]), "r"(a[mt][2]), "r"(a[mt][3]),
                          "r"(b[nt][0]), "r"(b[nt][1]));
        }
        __syncthreads();
    }
#undef ISSUE

    // ---- Epilogue: bias + activation, write float2 pairs to the gate table ----
    const bool is_f = (n0 >= 256);
    float* table = is_f ? g_Gf : g_Gz;
    const int ncol0 = n0 & 255;

    #pragma unroll
    for (int mt = 0; mt < 4; mt++) {
        int m = m0 + warp_m * 64 + mt * 16 + (lane >> 2);
        #pragma unroll
        for (int nt = 0; nt < 4; nt++) {
            int nloc = warp_n * 32 + nt * 8 + (lane & 3) * 2;
            float v00 = c[mt][nt][0] + sbias[nloc];
            float v01 = c[mt][nt][1] + sbias[nloc + 1];
            float v10 = c[mt][nt][2] + sbias[nloc];
            float v11 = c[mt][nt][3] + sbias[nloc + 1];
            float2 o0, o1;
            if (!is_f) {
                o0.x = tanhf(v00); o0.y = tanhf(v01);
                o1.x = tanhf(v10); o1.y = tanhf(v11);
            } else {
                o0.x = 1.f / (1.f + expf(-v00)); o0.y = 1.f / (1.f + expf(-v01));
                o1.x = 1.f / (1.f + expf(-v10)); o1.y = 1.f / (1.f + expf(-v11));
            }
            *(float2*)(table + (size_t)m * H_DIM + ncol0 + nloc)       = o0;
            *(float2*)(table + (size_t)(m + 8) * H_DIM + ncol0 + nloc) = o1;
        }
    }
}

// ---------------------------------------------------------------------------
// Kernel 2: parallel chunked scan (unchanged from passing R4 version).
// ---------------------------------------------------------------------------
__global__ __launch_bounds__(256) void scan_chunks(const int* __restrict__ X)
{
    const int chunk = blockIdx.x;
    const int b     = blockIdx.y;
    const int h     = threadIdx.x;

    __shared__ int toks[TC];
    if (h < TC) toks[h] = __ldg(&X[b * T_LEN + chunk * TC + h]);
    __syncthreads();

    float A = 1.f, Bc = 0.f;
    #pragma unroll 16
    for (int t = 0; t < TC; t++) {
        size_t base = (size_t)toks[t] * H_DIM + h;
        float f = __ldg(&g_Gf[base]);
        float z = __ldg(&g_Gz[base]);
        A *= f;
        Bc = fmaf(f, Bc - z, z);
    }

    int idx = (b * NCH + chunk) * H_DIM + h;
    g_cA[idx] = A;
    g_cB[idx] = Bc;
}

// ---------------------------------------------------------------------------
// Kernel 3: chunk combine + o-gate + output projection (unchanged).
// ---------------------------------------------------------------------------
__global__ __launch_bounds__(256) void finalize(
    const int*   __restrict__ X,
    const float* __restrict__ emb,
    const float* __restrict__ W,
    const float* __restrict__ bias,
    const float* __restrict__ c0,
    const float* __restrict__ Wout,
    const float* __restrict__ bout,
    float*       __restrict__ out)
{
    const int b = blockIdx.x;
    const int h = threadIdx.x;

    __shared__ float xrow[E_DIM];
    __shared__ float red[H_DIM];

    const int tok_last = X[b * T_LEN + (T_LEN - 1)];
    xrow[h] = emb[(size_t)tok_last * E_DIM + h];
    __syncthreads();

    float c = c0[b * H_DIM + h];
    #pragma unroll
    for (int j = 0; j < NCH; j++) {
        int idx = (b * NCH + j) * H_DIM + h;
        c = fmaf(g_cA[idx], c, g_cB[idx]);
    }

    float a0 = bias[512 + h], a1 = 0.f, a2 = 0.f, a3 = 0.f;
    #pragma unroll 8
    for (int e = 0; e < E_DIM; e += 4) {
        a0 = fmaf(xrow[e + 0], W[(size_t)(e + 0) * 768 + 512 + h], a0);
        a1 = fmaf(xrow[e + 1], W[(size_t)(e + 1) * 768 + 512 + h], a1);
        a2 = fmaf(xrow[e + 2], W[(size_t)(e + 2) * 768 + 512 + h], a2);
        a3 = fmaf(xrow[e + 3], W[(size_t)(e + 3) * 768 + 512 + h], a3);
    }
    float go = (a0 + a1) + (a2 + a3);
    float o  = 1.f / (1.f + expf(-go));

    red[h] = o * c * Wout[h];
    __syncthreads();

    #pragma unroll
    for (int s = 128; s > 0; s >>= 1) {
        if (h < s) red[h] += red[h + s];
        __syncthreads();
    }
    if (h == 0) out[b] = red[0] + bout[0];
}

// ---------------------------------------------------------------------------
extern "C" void kernel_launch(void* const* d_in, const int* in_sizes, int n_in,
                              void* d_out, int out_size)
{
    const int*   X    = (const int*)  d_in[0];   // [B, T] int32
    const float* emb  = (const float*)d_in[1];   // [VOCAB, E]
    const float* Wq   = (const float*)d_in[2];   // [E, 3H]
    const float* bq   = (const float*)d_in[3];   // [3H]
    const float* c0   = (const float*)d_in[4];   // [B, H]
    const float* Wout = (const float*)d_in[5];   // [H, 1]
    const float* bout = (const float*)d_in[6];   // [1]
    float*       out  = (float*)d_out;           // [B, 1]

    (void)in_sizes; (void)n_in; (void)out_size;

    // 0) bf16 split conversions (A': [Ah|Al], B': [Bh|Bh|Bl])
    convert_A<<<VOCAB * 64 / 256, 256>>>(emb);   // 8000 blocks
    convert_B<<<256, 512>>>(Wq);

    // 1) Gate-table GEMM on tensor cores (z + f), K'=768 bf16 split
    dim3 ggrid(4, VOCAB / 128);                  // (4, 250)
    gemm_gates_mma<<<ggrid, 256>>>(bq);

    // 2) Parallel chunked scan over time
    dim3 sgrid(NCH, BATCH);                      // (16, 64)
    scan_chunks<<<sgrid, 256>>>(X);

    // 3) Combine + o-gate + output projection
    finalize<<<BATCH, 256>>>(X, emb, Wq, bq, c0, Wout, bout, out);
}

// round 9
// speedup vs baseline: 1.7951x; 1.1559x over previous
#include <cuda_runtime.h>
#include <cuda_bf16.h>
#include <math.h>
#include <stdint.h>

// Problem constants
#define VOCAB 32000
#define E_DIM 256
#define H_DIM 256
#define BATCH 64
#define T_LEN 2048
#define NCH 16                 // time chunks for parallel scan
#define TC (T_LEN / NCH)       // 128 timesteps per chunk

// ---------------- device scratch (allocation-free contract) ----------------
// Interleaved gate table: g_Gfz[v*256 + h] = (tanh(z), sigmoid(f)), 64 MB
__device__ float2 g_Gfz[(size_t)VOCAB * H_DIM];
__device__ float g_cA[BATCH * NCH * H_DIM];          // per-chunk scan coeff A
__device__ float g_cB[BATCH * NCH * H_DIM];          // per-chunk scan coeff B
__device__ __nv_bfloat16 g_Abf[(size_t)VOCAB * 512]; // [Ah(256) | Al(256)] per row
// B' rows j=0..511 interleaved (j=2h -> z col h, j=2h+1 -> f col h),
// along K': [Bh(256) | Bh(256) | Bl(256)]
__device__ __nv_bfloat16 g_Bbf[(size_t)512 * 768];

static __device__ __forceinline__ uint32_t smem_u32(const void* p) {
    uint32_t a;
    asm("{ .reg .u64 t; cvta.to.shared.u64 t, %1; cvt.u32.u64 %0, t; }" : "=r"(a) : "l"(p));
    return a;
}

// ===========================================================================
// Convert kernels: fp32 -> 2-term bf16 split, GEMM-friendly layouts.
// ===========================================================================
__global__ __launch_bounds__(256) void convert_A(const float* __restrict__ emb)
{
    int idx = blockIdx.x * 256 + threadIdx.x;   // one float4 each; 32000*64 total
    int v = idx >> 6;
    int k = (idx & 63) * 4;
    float4 x = *(const float4*)(emb + (size_t)v * E_DIM + k);
    __nv_bfloat162 h01 = __floats2bfloat162_rn(x.x, x.y);
    __nv_bfloat162 h23 = __floats2bfloat162_rn(x.z, x.w);
    __nv_bfloat162 l01 = __floats2bfloat162_rn(x.x - __bfloat162float(h01.x),
                                               x.y - __bfloat162float(h01.y));
    __nv_bfloat162 l23 = __floats2bfloat162_rn(x.z - __bfloat162float(h23.x),
                                               x.w - __bfloat162float(h23.y));
    __nv_bfloat16* row = g_Abf + (size_t)v * 512;
    *(__nv_bfloat162*)(row + k)           = h01;
    *(__nv_bfloat162*)(row + k + 2)       = h23;
    *(__nv_bfloat162*)(row + 256 + k)     = l01;
    *(__nv_bfloat162*)(row + 256 + k + 2) = l23;
}

__global__ __launch_bounds__(512) void convert_B(const float* __restrict__ W)
{
    int k = blockIdx.x;          // 0..255 (W row)
    int j = threadIdx.x;         // 0..511 interleaved output row
    int src = (j & 1) * 256 + (j >> 1);   // z cols 0..255, f cols 256..511
    float v = W[(size_t)k * 768 + src];
    __nv_bfloat16 h = __float2bfloat16(v);
    __nv_bfloat16 l = __float2bfloat16(v - __bfloat162float(h));
    __nv_bfloat16* row = g_Bbf + (size_t)j * 768;
    row[k]       = h;   // pairs with Ah (iters 0-15: [Ah|Al])
    row[k + 256] = h;   // pairs with Al
    row[k + 512] = l;   // pairs with Ah (iters 16-23 remap)
}

// ===========================================================================
// Kernel 1: bf16 split GEMM on mma.sync m16n8k16, 4-stage cp.async pipeline,
// one __syncthreads per K-iteration. Per CTA: D[128 x 128] over K'=768.
// Dynamic smem: 4 stages x (A 10240B + B 10240B) + bias = 82432 B.
// ===========================================================================
#define STG   20480              // per-stage stride (A tile + B tile)
#define BOFF  10240              // B tile offset within a stage
#define SBIAS 81920              // bias offset
#define SMTOT (SBIAS + 512)

__global__ __launch_bounds__(256, 2) void gemm_gates_mma(const float* __restrict__ bias)
{
    extern __shared__ __align__(128) char dsm[];
    float* sbias = (float*)(dsm + SBIAS);

    const int tid  = threadIdx.x;
    const int lane = tid & 31;
    const int wid  = tid >> 5;
    const int n0   = blockIdx.x * 128;   // interleaved col block (z/f mixed)
    const int m0   = blockIdx.y * 128;   // vocab row base
    const int warp_m = wid & 1;
    const int warp_n = wid >> 1;

    if (tid < 128) {
        int j = n0 + tid;
        sbias[tid] = bias[(j & 1) * 256 + (j >> 1)];
    }

    const uint32_t sbase = smem_u32(dsm);

    // cp.async mapping: per tile 512 16B-chunks; row = tid>>2 (+64), chunk = tid&3
    const int ld_row = tid >> 2;
    const int ld_chk = tid & 3;

    float c[4][4][4];
    #pragma unroll
    for (int i = 0; i < 4; i++)
        #pragma unroll
        for (int j = 0; j < 4; j++)
            #pragma unroll
            for (int q = 0; q < 4; q++) c[i][j][q] = 0.f;

    // ldmatrix lane-dependent base byte-offsets (stage offset added later)
    const uint32_t a_lm = (uint32_t)((warp_m * 64 + (lane & 15)) * 80 + (lane >> 4) * 16);
    const uint32_t b_lm = (uint32_t)((warp_n * 32 + (lane >> 4) * 8 + (lane & 7)) * 80
                                     + ((lane >> 3) & 1) * 16);

#define ISSUE(it) do {                                                             \
    if ((it) < 24) {                                                               \
        int buf_ = (it) & 3;                                                       \
        int kA_ = (((it) < 16) ? (it) : (it) - 16) * 32;                           \
        int kB_ = (it) * 32;                                                       \
        _Pragma("unroll")                                                          \
        for (int r_ = 0; r_ < 2; r_++) {                                           \
            int row_ = ld_row + r_ * 64;                                           \
            uint32_t da_ = sbase + buf_ * STG + row_ * 80 + ld_chk * 16;           \
            const __nv_bfloat16* ga_ = g_Abf + (size_t)(m0 + row_) * 512 + kA_ + ld_chk * 8; \
            asm volatile("cp.async.cg.shared.global [%0], [%1], 16;" :: "r"(da_), "l"(ga_)); \
            uint32_t db_ = sbase + buf_ * STG + BOFF + row_ * 80 + ld_chk * 16;    \
            const __nv_bfloat16* gb_ = g_Bbf + (size_t)(n0 + row_) * 768 + kB_ + ld_chk * 8; \
            asm volatile("cp.async.cg.shared.global [%0], [%1], 16;" :: "r"(db_), "l"(gb_)); \
        }                                                                          \
    }                                                                              \
    asm volatile("cp.async.commit_group;");                                        \
} while (0)

    ISSUE(0); ISSUE(1); ISSUE(2);

    for (int it = 0; it < 24; ++it) {
        const int buf = it & 3;
        asm volatile("cp.async.wait_group 2;");
        __syncthreads();              // stage `it` visible; all warps done with it-1
        ISSUE(it + 3);                // fills buf (it-1)&3 — safe after the sync

        #pragma unroll
        for (int ks = 0; ks < 2; ks++) {
            uint32_t a[4][4], b[4][2];
            #pragma unroll
            for (int mt = 0; mt < 4; mt++) {
                uint32_t addr = sbase + buf * STG + a_lm + mt * (16 * 80) + ks * 32;
                asm volatile("ldmatrix.sync.aligned.m8n8.x4.shared.b16 {%0,%1,%2,%3}, [%4];"
                             : "=r"(a[mt][0]), "=r"(a[mt][1]), "=r"(a[mt][2]), "=r"(a[mt][3])
                             : "r"(addr));
            }
            #pragma unroll
            for (int np = 0; np < 2; np++) {
                uint32_t addr = sbase + buf * STG + BOFF + b_lm + np * (16 * 80) + ks * 32;
                asm volatile("ldmatrix.sync.aligned.m8n8.x4.shared.b16 {%0,%1,%2,%3}, [%4];"
                             : "=r"(b[np * 2][0]), "=r"(b[np * 2][1]),
                               "=r"(b[np * 2 + 1][0]), "=r"(b[np * 2 + 1][1])
                             : "r"(addr));
            }
            #pragma unroll
            for (int mt = 0; mt < 4; mt++)
                #pragma unroll
                for (int nt = 0; nt < 4; nt++)
                    asm volatile(
                        "mma.sync.aligned.m16n8k16.row.col.f32.bf16.bf16.f32 "
                        "{%0,%1,%2,%3}, {%4,%5,%6,%7}, {%8,%9}, {%0,%1,%2,%3};"
                        : "+f"(c[mt][nt][0]), "+f"(c[mt][nt][1]),
                          "+f"(c[mt][nt][2]), "+f"(c[mt][nt][3])
                        : "r"(a[mt][0]), "r"(a[mt][1]), "r"(a[mt][2]), "r"(a[mt][3]),
                          "r"(b[nt][0]), "r"(b[nt][1]));
        }
    }
#undef ISSUE

    // ---- Epilogue: bias + activation, one float2 (z,f) per h to g_Gfz ----
    #pragma unroll
    for (int mt = 0; mt < 4; mt++) {
        int m = m0 + warp_m * 64 + mt * 16 + (lane >> 2);
        #pragma unroll
        for (int nt = 0; nt < 4; nt++) {
            int nloc = warp_n * 32 + nt * 8 + (lane & 3) * 2;   // even = z, odd = f
            int h = (n0 + nloc) >> 1;
            float vz0 = c[mt][nt][0] + sbias[nloc];
            float vf0 = c[mt][nt][1] + sbias[nloc + 1];
            float vz1 = c[mt][nt][2] + sbias[nloc];
            float vf1 = c[mt][nt][3] + sbias[nloc + 1];
            float2 o0, o1;
            o0.x = tanhf(vz0); o0.y = 1.f / (1.f + expf(-vf0));
            o1.x = tanhf(vz1); o1.y = 1.f / (1.f + expf(-vf1));
            g_Gfz[(size_t)m * H_DIM + h]       = o0;
            g_Gfz[(size_t)(m + 8) * H_DIM + h] = o1;
        }
    }
}

// ---------------------------------------------------------------------------
// Kernel 2: parallel chunked scan; one 8B gather per (t,h) from g_Gfz.
// ---------------------------------------------------------------------------
__global__ __launch_bounds__(256) void scan_chunks(const int* __restrict__ X)
{
    const int chunk = blockIdx.x;
    const int b     = blockIdx.y;
    const int h     = threadIdx.x;

    __shared__ int toks[TC];
    if (h < TC) toks[h] = __ldg(&X[b * T_LEN + chunk * TC + h]);
    __syncthreads();

    float A = 1.f, Bc = 0.f;
    #pragma unroll 16
    for (int t = 0; t < TC; t++) {
        float2 p = __ldg(&g_Gfz[(size_t)toks[t] * H_DIM + h]);
        float z = p.x, f = p.y;
        A *= f;
        Bc = fmaf(f, Bc - z, z);
    }

    int idx = (b * NCH + chunk) * H_DIM + h;
    g_cA[idx] = A;
    g_cB[idx] = Bc;
}

// ---------------------------------------------------------------------------
// Kernel 3: chunk combine + o-gate + output projection (unchanged).
// ---------------------------------------------------------------------------
__global__ __launch_bounds__(256) void finalize(
    const int*   __restrict__ X,
    const float* __restrict__ emb,
    const float* __restrict__ W,
    const float* __restrict__ bias,
    const float* __restrict__ c0,
    const float* __restrict__ Wout,
    const float* __restrict__ bout,
    float*       __restrict__ out)
{
    const int b = blockIdx.x;
    const int h = threadIdx.x;

    __shared__ float xrow[E_DIM];
    __shared__ float red[H_DIM];

    const int tok_last = X[b * T_LEN + (T_LEN - 1)];
    xrow[h] = emb[(size_t)tok_last * E_DIM + h];
    __syncthreads();

    float c = c0[b * H_DIM + h];
    #pragma unroll
    for (int j = 0; j < NCH; j++) {
        int idx = (b * NCH + j) * H_DIM + h;
        c = fmaf(g_cA[idx], c, g_cB[idx]);
    }

    float a0 = bias[512 + h], a1 = 0.f, a2 = 0.f, a3 = 0.f;
    #pragma unroll 8
    for (int e = 0; e < E_DIM; e += 4) {
        a0 = fmaf(xrow[e + 0], W[(size_t)(e + 0) * 768 + 512 + h], a0);
        a1 = fmaf(xrow[e + 1], W[(size_t)(e + 1) * 768 + 512 + h], a1);
        a2 = fmaf(xrow[e + 2], W[(size_t)(e + 2) * 768 + 512 + h], a2);
        a3 = fmaf(xrow[e + 3], W[(size_t)(e + 3) * 768 + 512 + h], a3);
    }
    float go = (a0 + a1) + (a2 + a3);
    float o  = 1.f / (1.f + expf(-go));

    red[h] = o * c * Wout[h];
    __syncthreads();

    #pragma unroll
    for (int s = 128; s > 0; s >>= 1) {
        if (h < s) red[h] += red[h + s];
        __syncthreads();
    }
    if (h == 0) out[b] = red[0] + bout[0];
}

// ---------------------------------------------------------------------------
extern "C" void kernel_launch(void* const* d_in, const int* in_sizes, int n_in,
                              void* d_out, int out_size)
{
    const int*   X    = (const int*)  d_in[0];   // [B, T] int32
    const float* emb  = (const float*)d_in[1];   // [VOCAB, E]
    const float* Wq   = (const float*)d_in[2];   // [E, 3H]
    const float* bq   = (const float*)d_in[3];   // [3H]
    const float* c0   = (const float*)d_in[4];   // [B, H]
    const float* Wout = (const float*)d_in[5];   // [H, 1]
    const float* bout = (const float*)d_in[6];   // [1]
    float*       out  = (float*)d_out;           // [B, 1]

    (void)in_sizes; (void)n_in; (void)out_size;

    cudaFuncSetAttribute(gemm_gates_mma, cudaFuncAttributeMaxDynamicSharedMemorySize, SMTOT);

    // 0) bf16 split conversions (A': [Ah|Al], B': interleaved [Bh|Bh|Bl])
    convert_A<<<VOCAB * 64 / 256, 256>>>(emb);   // 8000 blocks
    convert_B<<<256, 512>>>(Wq);

    // 1) Gate-table GEMM on tensor cores, K'=768 bf16 split, 4-stage pipeline
    dim3 ggrid(4, VOCAB / 128);                  // (4, 250)
    gemm_gates_mma<<<ggrid, 256, SMTOT>>>(bq);

    // 2) Parallel chunked scan over time
    dim3 sgrid(NCH, BATCH);                      // (16, 64)
    scan_chunks<<<sgrid, 256>>>(X);

    // 3) Combine + o-gate + output projection
    finalize<<<BATCH, 256>>>(X, emb, Wq, bq, c0, Wout, bout, out);
}

// round 11
// speedup vs baseline: 2.1505x; 1.1980x over previous
#include <cuda_runtime.h>
#include <cuda_fp16.h>
#include <math.h>
#include <stdint.h>

// Problem constants
#define VOCAB 32000
#define E_DIM 256
#define H_DIM 256
#define BATCH 64
#define T_LEN 2048
#define NCH 16                 // time chunks for parallel scan
#define TC (T_LEN / NCH)       // 128 timesteps per chunk

// ---------------- device scratch (allocation-free contract) ----------------
// Interleaved gate table: g_Gfz[v*256 + h] = (tanh(z), sigmoid(f)), 64 MB fp32
__device__ float2 g_Gfz[(size_t)VOCAB * H_DIM];
__device__ float g_cA[BATCH * NCH * H_DIM];          // per-chunk scan coeff A
__device__ float g_cB[BATCH * NCH * H_DIM];          // per-chunk scan coeff B
// A' = [Ah(256) | Al(256)] fp16 per vocab row (2-term split of emb)
__device__ __half g_Ahf[(size_t)VOCAB * 512];
// B' rows j=0..511 interleaved (j=2h -> z col h, j=2h+1 -> f col h),
// along K': [Bh(256) | Bh(256)] (duplicate so kB = kA, fully linear)
__device__ __half g_Bhf[(size_t)512 * 512];

static __device__ __forceinline__ uint32_t smem_u32(const void* p) {
    uint32_t a;
    asm("{ .reg .u64 t; cvta.to.shared.u64 t, %1; cvt.u32.u64 %0, t; }" : "=r"(a) : "l"(p));
    return a;
}

// ===========================================================================
// Convert kernels: fp32 -> 2-term fp16 split, GEMM-friendly layouts.
// ===========================================================================
__global__ __launch_bounds__(256) void convert_A(const float* __restrict__ emb)
{
    int idx = blockIdx.x * 256 + threadIdx.x;   // one float4 each; 32000*64 total
    int v = idx >> 6;
    int k = (idx & 63) * 4;
    float4 x = *(const float4*)(emb + (size_t)v * E_DIM + k);
    __half2 h01 = __floats2half2_rn(x.x, x.y);
    __half2 h23 = __floats2half2_rn(x.z, x.w);
    __half2 l01 = __floats2half2_rn(x.x - __half2float(__low2half(h01)),
                                    x.y - __half2float(__high2half(h01)));
    __half2 l23 = __floats2half2_rn(x.z - __half2float(__low2half(h23)),
                                    x.w - __half2float(__high2half(h23)));
    __half* row = g_Ahf + (size_t)v * 512;
    *(__half2*)(row + k)           = h01;
    *(__half2*)(row + k + 2)       = h23;
    *(__half2*)(row + 256 + k)     = l01;
    *(__half2*)(row + 256 + k + 2) = l23;
}

__global__ __launch_bounds__(512) void convert_B(const float* __restrict__ W)
{
    int k = blockIdx.x;          // 0..255 (W row)
    int j = threadIdx.x;         // 0..511 interleaved output row
    int src = (j & 1) * 256 + (j >> 1);   // even j -> z col, odd j -> f col
    float v = W[(size_t)k * 768 + src];
    __half h = __float2half(v);
    __half* row = g_Bhf + (size_t)j * 512;
    row[k]       = h;   // pairs with Ah (iters 0-7)
    row[k + 256] = h;   // pairs with Al (iters 8-15)
}

// ===========================================================================
// Kernel 1: fp16 2-term split GEMM on mma.sync m16n8k16, 4-stage cp.async
// pipeline, one __syncthreads per K-iteration. Per CTA: D[128x128], K'=512
// (16 iters of BK=32). Dynamic smem: 4 x (A 10240 + B 10240) + bias.
// ===========================================================================
#define STG   20480              // per-stage stride (A tile + B tile)
#define BOFF  10240              // B tile offset within a stage
#define SBIAS 81920              // bias offset
#define SMTOT (SBIAS + 512)
#define NKIT  16

__global__ __launch_bounds__(256, 2) void gemm_gates_mma(const float* __restrict__ bias)
{
    extern __shared__ __align__(128) char dsm[];
    float* sbias = (float*)(dsm + SBIAS);

    const int tid  = threadIdx.x;
    const int lane = tid & 31;
    const int wid  = tid >> 5;
    const int n0   = blockIdx.x * 128;   // interleaved col block (z/f mixed)
    const int m0   = blockIdx.y * 128;   // vocab row base
    const int warp_m = wid & 1;
    const int warp_n = wid >> 1;

    if (tid < 128) {
        int j = n0 + tid;
        sbias[tid] = bias[(j & 1) * 256 + (j >> 1)];
    }

    const uint32_t sbase = smem_u32(dsm);

    // cp.async mapping: per tile 512 16B-chunks; row = tid>>2 (+64), chunk = tid&3
    const int ld_row = tid >> 2;
    const int ld_chk = tid & 3;

    float c[4][4][4];
    #pragma unroll
    for (int i = 0; i < 4; i++)
        #pragma unroll
        for (int j = 0; j < 4; j++)
            #pragma unroll
            for (int q = 0; q < 4; q++) c[i][j][q] = 0.f;

    // ldmatrix lane-dependent base byte-offsets (stage offset added later)
    const uint32_t a_lm = (uint32_t)((warp_m * 64 + (lane & 15)) * 80 + (lane >> 4) * 16);
    const uint32_t b_lm = (uint32_t)((warp_n * 32 + (lane >> 4) * 8 + (lane & 7)) * 80
                                     + ((lane >> 3) & 1) * 16);

#define ISSUE(it) do {                                                             \
    if ((it) < NKIT) {                                                             \
        int buf_ = (it) & 3;                                                       \
        int kk_ = (it) * 32;                                                       \
        _Pragma("unroll")                                                          \
        for (int r_ = 0; r_ < 2; r_++) {                                           \
            int row_ = ld_row + r_ * 64;                                           \
            uint32_t da_ = sbase + buf_ * STG + row_ * 80 + ld_chk * 16;           \
            const __half* ga_ = g_Ahf + (size_t)(m0 + row_) * 512 + kk_ + ld_chk * 8; \
            asm volatile("cp.async.cg.shared.global [%0], [%1], 16;" :: "r"(da_), "l"(ga_)); \
            uint32_t db_ = sbase + buf_ * STG + BOFF + row_ * 80 + ld_chk * 16;    \
            const __half* gb_ = g_Bhf + (size_t)(n0 + row_) * 512 + kk_ + ld_chk * 8; \
            asm volatile("cp.async.cg.shared.global [%0], [%1], 16;" :: "r"(db_), "l"(gb_)); \
        }                                                                          \
    }                                                                              \
    asm volatile("cp.async.commit_group;");                                        \
} while (0)

    ISSUE(0); ISSUE(1); ISSUE(2);

    for (int it = 0; it < NKIT; ++it) {
        const int buf = it & 3;
        asm volatile("cp.async.wait_group 2;");
        __syncthreads();              // stage `it` visible; all warps done with it-1
        ISSUE(it + 3);                // fills buf (it-1)&3 — safe after the sync

        #pragma unroll
        for (int ks = 0; ks < 2; ks++) {
            uint32_t a[4][4], b[4][2];
            #pragma unroll
            for (int mt = 0; mt < 4; mt++) {
                uint32_t addr = sbase + buf * STG + a_lm + mt * (16 * 80) + ks * 32;
                asm volatile("ldmatrix.sync.aligned.m8n8.x4.shared.b16 {%0,%1,%2,%3}, [%4];"
                             : "=r"(a[mt][0]), "=r"(a[mt][1]), "=r"(a[mt][2]), "=r"(a[mt][3])
                             : "r"(addr));
            }
            #pragma unroll
            for (int np = 0; np < 2; np++) {
                uint32_t addr = sbase + buf * STG + BOFF + b_lm + np * (16 * 80) + ks * 32;
                asm volatile("ldmatrix.sync.aligned.m8n8.x4.shared.b16 {%0,%1,%2,%3}, [%4];"
                             : "=r"(b[np * 2][0]), "=r"(b[np * 2][1]),
                               "=r"(b[np * 2 + 1][0]), "=r"(b[np * 2 + 1][1])
                             : "r"(addr));
            }
            #pragma unroll
            for (int mt = 0; mt < 4; mt++)
                #pragma unroll
                for (int nt = 0; nt < 4; nt++)
                    asm volatile(
                        "mma.sync.aligned.m16n8k16.row.col.f32.f16.f16.f32 "
                        "{%0,%1,%2,%3}, {%4,%5,%6,%7}, {%8,%9}, {%0,%1,%2,%3};"
                        : "+f"(c[mt][nt][0]), "+f"(c[mt][nt][1]),
                          "+f"(c[mt][nt][2]), "+f"(c[mt][nt][3])
                        : "r"(a[mt][0]), "r"(a[mt][1]), "r"(a[mt][2]), "r"(a[mt][3]),
                          "r"(b[nt][0]), "r"(b[nt][1]));
        }
    }
#undef ISSUE

    // ---- Epilogue: bias + activation, one float2 (z,f) per h to g_Gfz ----
    #pragma unroll
    for (int mt = 0; mt < 4; mt++) {
        int m = m0 + warp_m * 64 + mt * 16 + (lane >> 2);
        #pragma unroll
        for (int nt = 0; nt < 4; nt++) {
            int nloc = warp_n * 32 + nt * 8 + (lane & 3) * 2;   // even = z, odd = f
            int h = (n0 + nloc) >> 1;
            float vz0 = c[mt][nt][0] + sbias[nloc];
            float vf0 = c[mt][nt][1] + sbias[nloc + 1];
            float vz1 = c[mt][nt][2] + sbias[nloc];
            float vf1 = c[mt][nt][3] + sbias[nloc + 1];
            float2 o0, o1;
            o0.x = tanhf(vz0); o0.y = 1.f / (1.f + expf(-vf0));
            o1.x = tanhf(vz1); o1.y = 1.f / (1.f + expf(-vf1));
            g_Gfz[(size_t)m * H_DIM + h]       = o0;
            g_Gfz[(size_t)(m + 8) * H_DIM + h] = o1;
        }
    }
}

// ---------------------------------------------------------------------------
// Kernel 2: parallel chunked scan; one 8B gather per (t,h) from g_Gfz.
// At the chip LTS cap (~12.4 TB/s achieved) — at its floor for an fp32 table.
// ---------------------------------------------------------------------------
__global__ __launch_bounds__(256) void scan_chunks(const int* __restrict__ X)
{
    const int chunk = blockIdx.x;
    const int b     = blockIdx.y;
    const int h     = threadIdx.x;

    __shared__ int toks[TC];
    if (h < TC) toks[h] = __ldg(&X[b * T_LEN + chunk * TC + h]);
    __syncthreads();

    float A = 1.f, Bc = 0.f;
    #pragma unroll 16
    for (int t = 0; t < TC; t++) {
        float2 p = __ldg(&g_Gfz[(size_t)toks[t] * H_DIM + h]);
        float z = p.x, f = p.y;
        A *= f;
        Bc = fmaf(f, Bc - z, z);
    }

    int idx = (b * NCH + chunk) * H_DIM + h;
    g_cA[idx] = A;
    g_cB[idx] = Bc;
}

// ---------------------------------------------------------------------------
// Kernel 3: chunk combine + o-gate + output projection (unchanged).
// ---------------------------------------------------------------------------
__global__ __launch_bounds__(256) void finalize(
    const int*   __restrict__ X,
    const float* __restrict__ emb,
    const float* __restrict__ W,
    const float* __restrict__ bias,
    const float* __restrict__ c0,
    const float* __restrict__ Wout,
    const float* __restrict__ bout,
    float*       __restrict__ out)
{
    const int b = blockIdx.x;
    const int h = threadIdx.x;

    __shared__ float xrow[E_DIM];
    __shared__ float red[H_DIM];

    const int tok_last = X[b * T_LEN + (T_LEN - 1)];
    xrow[h] = emb[(size_t)tok_last * E_DIM + h];
    __syncthreads();

    float c = c0[b * H_DIM + h];
    #pragma unroll
    for (int j = 0; j < NCH; j++) {
        int idx = (b * NCH + j) * H_DIM + h;
        c = fmaf(g_cA[idx], c, g_cB[idx]);
    }

    float a0 = bias[512 + h], a1 = 0.f, a2 = 0.f, a3 = 0.f;
    #pragma unroll 8
    for (int e = 0; e < E_DIM; e += 4) {
        a0 = fmaf(xrow[e + 0], W[(size_t)(e + 0) * 768 + 512 + h], a0);
        a1 = fmaf(xrow[e + 1], W[(size_t)(e + 1) * 768 + 512 + h], a1);
        a2 = fmaf(xrow[e + 2], W[(size_t)(e + 2) * 768 + 512 + h], a2);
        a3 = fmaf(xrow[e + 3], W[(size_t)(e + 3) * 768 + 512 + h], a3);
    }
    float go = (a0 + a1) + (a2 + a3);
    float o  = 1.f / (1.f + expf(-go));

    red[h] = o * c * Wout[h];
    __syncthreads();

    #pragma unroll
    for (int s = 128; s > 0; s >>= 1) {
        if (h < s) red[h] += red[h + s];
        __syncthreads();
    }
    if (h == 0) out[b] = red[0] + bout[0];
}

// ---------------------------------------------------------------------------
extern "C" void kernel_launch(void* const* d_in, const int* in_sizes, int n_in,
                              void* d_out, int out_size)
{
    const int*   X    = (const int*)  d_in[0];   // [B, T] int32
    const float* emb  = (const float*)d_in[1];   // [VOCAB, E]
    const float* Wq   = (const float*)d_in[2];   // [E, 3H]
    const float* bq   = (const float*)d_in[3];   // [3H]
    const float* c0   = (const float*)d_in[4];   // [B, H]
    const float* Wout = (const float*)d_in[5];   // [H, 1]
    const float* bout = (const float*)d_in[6];   // [1]
    float*       out  = (float*)d_out;           // [B, 1]

    (void)in_sizes; (void)n_in; (void)out_size;

    cudaFuncSetAttribute(gemm_gates_mma, cudaFuncAttributeMaxDynamicSharedMemorySize, SMTOT);

    // 0) fp16 split conversions (A': [Ah|Al], B': interleaved [Bh|Bh])
    convert_A<<<VOCAB * 64 / 256, 256>>>(emb);   // 8000 blocks
    convert_B<<<256, 512>>>(Wq);

    // 1) Gate-table GEMM on tensor cores, K'=512 fp16 2-term split
    dim3 ggrid(4, VOCAB / 128);                  // (4, 250)
    gemm_gates_mma<<<ggrid, 256, SMTOT>>>(bq);

    // 2) Parallel chunked scan over time
    dim3 sgrid(NCH, BATCH);                      // (16, 64)
    scan_chunks<<<sgrid, 256>>>(X);

    // 3) Combine + o-gate + output projection
    finalize<<<BATCH, 256>>>(X, emb, Wq, bq, c0, Wout, bout, out);
}